// round 9
// baseline (speedup 1.0000x reference)
#include <cuda_runtime.h>
#include <math.h>
#include <stdint.h>

#define OBS_DIM 256
#define ACT_DIM 64
#define T_TOT   22
#define HID     32
#define MAXW    15
#define NSTEP   15
#define NGATE   96
#define KDIM    320
#define MAXB    8192

// GRU pre-activation scratch: GI[(b*15+t)*96 + g]
__device__ float g_GI[(size_t)MAXB * NSTEP * NGATE];

// ---------- packed f32x2 helpers ----------
__device__ __forceinline__ unsigned long long pk2(float lo, float hi) {
    unsigned long long r;
    asm("mov.b64 %0, {%1, %2};" : "=l"(r) : "f"(lo), "f"(hi));
    return r;
}
__device__ __forceinline__ void upk2(unsigned long long v, float& lo, float& hi) {
    asm("mov.b64 {%0, %1}, %2;" : "=f"(lo), "=f"(hi) : "l"(v));
}
__device__ __forceinline__ unsigned long long ffma2(unsigned long long a,
                                                    unsigned long long b,
                                                    unsigned long long c) {
    unsigned long long d;
    asm("fma.rn.f32x2 %0, %1, %2, %3;" : "=l"(d) : "l"(a), "l"(b), "l"(c));
    return d;
}

__device__ __forceinline__ float wsum(float x) {
#pragma unroll
    for (int o = 16; o; o >>= 1) x += __shfl_xor_sync(0xffffffffu, x, o);
    return x;
}
__device__ __forceinline__ float wmax(float x) {
#pragma unroll
    for (int o = 16; o; o >>= 1) x = fmaxf(x, __shfl_xor_sync(0xffffffffu, x, o));
    return x;
}
__device__ __forceinline__ float sigm(float x) { return 1.f / (1.f + __expf(-x)); }
__device__ __forceinline__ float tanh_fast(float x) {
    float e = __expf(-2.f * fabsf(x));
    float r = (1.f - e) / (1.f + e);
    return copysignf(r, x);
}

// =====================================================================
// Kernel 1 (R2 known-good, 171us): GI = X @ W_ih^T + b_ih
// =====================================================================
#define BM 128
#define BK 32

__global__ __launch_bounds__(128, 3) void k_gemm(
    const float* __restrict__ obs, const float* __restrict__ act,
    const float* __restrict__ Wih, const float* __restrict__ bih, int Bn)
{
    __shared__ __align__(16) float Xs[BM][33];
    __shared__ __align__(16) float Ws[BK][100];

    const int Mtot = Bn * NSTEP;
    const int tid = threadIdx.x;
    const int tx = tid & 7, ty = tid >> 3;
    const int m_base = blockIdx.x * BM;
    const int lm  = tid >> 3;
    const int lk4 = tid & 7;

    const int n0 = tx * 12, m0 = ty * 8;

    unsigned long long acc[8][6];
#pragma unroll
    for (int i = 0; i < 8; i++)
#pragma unroll
        for (int p = 0; p < 6; p++) acc[i][p] = 0ULL;

    for (int kt = 0; kt < KDIM; kt += BK) {
#pragma unroll
        for (int pass = 0; pass < 8; pass++) {
            int m  = lm + 16 * pass;
            int gm = m_base + m;
            int gmc = gm < Mtot ? gm : Mtot - 1;
            int bb = gmc / NSTEP;
            int tt = gmc - bb * NSTEP;
            int k0 = kt + 4 * lk4;
            float4 v;
            if (kt < OBS_DIM)
                v = *(const float4*)(obs + ((size_t)(bb * T_TOT + tt)) * OBS_DIM + k0);
            else
                v = *(const float4*)(act + ((size_t)(bb * T_TOT + tt)) * ACT_DIM + (k0 - OBS_DIM));
            Xs[m][4 * lk4 + 0] = v.x;
            Xs[m][4 * lk4 + 1] = v.y;
            Xs[m][4 * lk4 + 2] = v.z;
            Xs[m][4 * lk4 + 3] = v.w;
        }
#pragma unroll
        for (int pass = 0; pass < 6; pass++) {
            int n = lm + 16 * pass;
            float4 v = *(const float4*)(Wih + (size_t)n * KDIM + kt + 4 * lk4);
            Ws[4 * lk4 + 0][n] = v.x;
            Ws[4 * lk4 + 1][n] = v.y;
            Ws[4 * lk4 + 2][n] = v.z;
            Ws[4 * lk4 + 3][n] = v.w;
        }
        __syncthreads();

#pragma unroll 8
        for (int k = 0; k < BK; k++) {
            float4 wa = *(const float4*)&Ws[k][n0];
            float4 wb = *(const float4*)&Ws[k][n0 + 4];
            float4 wc = *(const float4*)&Ws[k][n0 + 8];
            unsigned long long w0 = pk2(wa.x, wa.y);
            unsigned long long w1 = pk2(wa.z, wa.w);
            unsigned long long w2 = pk2(wb.x, wb.y);
            unsigned long long w3 = pk2(wb.z, wb.w);
            unsigned long long w4 = pk2(wc.x, wc.y);
            unsigned long long w5 = pk2(wc.z, wc.w);
#pragma unroll
            for (int i = 0; i < 8; i++) {
                float x = Xs[m0 + i][k];
                unsigned long long xx = pk2(x, x);
                acc[i][0] = ffma2(xx, w0, acc[i][0]);
                acc[i][1] = ffma2(xx, w1, acc[i][1]);
                acc[i][2] = ffma2(xx, w2, acc[i][2]);
                acc[i][3] = ffma2(xx, w3, acc[i][3]);
                acc[i][4] = ffma2(xx, w4, acc[i][4]);
                acc[i][5] = ffma2(xx, w5, acc[i][5]);
            }
        }
        __syncthreads();
    }

    float4 bv0 = *(const float4*)(bih + n0);
    float4 bv1 = *(const float4*)(bih + n0 + 4);
    float4 bv2 = *(const float4*)(bih + n0 + 8);

#pragma unroll
    for (int i = 0; i < 8; i++) {
        int gm = m_base + m0 + i;
        if (gm >= Mtot) continue;
        float f[12];
#pragma unroll
        for (int p = 0; p < 6; p++) upk2(acc[i][p], f[2 * p], f[2 * p + 1]);
        float4 o0 = make_float4(f[0] + bv0.x, f[1] + bv0.y, f[2] + bv0.z, f[3] + bv0.w);
        float4 o1 = make_float4(f[4] + bv1.x, f[5] + bv1.y, f[6] + bv1.z, f[7] + bv1.w);
        float4 o2 = make_float4(f[8] + bv2.x, f[9] + bv2.y, f[10] + bv2.z, f[11] + bv2.w);
        float* dst = g_GI + (size_t)gm * NGATE + n0;
        *(float4*)(dst + 0) = o0;
        *(float4*)(dst + 4) = o1;
        *(float4*)(dst + 8) = o2;
    }
}

// =====================================================================
// Kernel 2 (fused, register-diet): features first, W_hh in smem,
// GRU + LN + MLP + argmax + mask + grouped window.
// =====================================================================
__global__ __launch_bounds__(256, 3) void k_fused(
    const float* __restrict__ obs, const float* __restrict__ act,
    const float* __restrict__ Whh, const float* __restrict__ bhh,
    const float* __restrict__ lng, const float* __restrict__ lnb,
    const float* __restrict__ W1, const float* __restrict__ b1,
    const float* __restrict__ W2, const float* __restrict__ b2,
    const float* __restrict__ W3, const float* __restrict__ b3,
    float* __restrict__ out, int Bn)
{
    __shared__ float whr[32][33], whz[32][33], whn[32][33];
    __shared__ float w1s[64 * 35];
    __shared__ float w2s[32 * 65];
    __shared__ float w3s[14 * 33];
    __shared__ float b1s[64], b2s[32], b3s[14];
    __shared__ float gms[35], bts[35];
    __shared__ float wbuf[8][144];
    __shared__ float hs[8][32];

    const int tid = threadIdx.x;
    // W_hh -> smem (shared by all warps; row j of each gate)
    for (int i = tid; i < 3 * HID * HID; i += 256) {
        int row = i >> 5, k = i & 31;
        float v = Whh[i];
        if (row < 32)       whr[row][k] = v;
        else if (row < 64)  whz[row - 32][k] = v;
        else                whn[row - 64][k] = v;
    }
    for (int i = tid; i < 64 * 35; i += 256) w1s[i] = W1[i];
    for (int i = tid; i < 32 * 64; i += 256) w2s[(i >> 6) * 65 + (i & 63)] = W2[i];
    for (int i = tid; i < 14 * 32; i += 256) w3s[(i >> 5) * 33 + (i & 31)] = W3[i];
    if (tid < 64) b1s[tid] = b1[tid];
    if (tid < 32) b2s[tid] = b2[tid];
    if (tid < 14) b3s[tid] = b3[tid];
    if (tid < 35) { gms[tid] = lng[tid]; bts[tid] = lnb[tid]; }
    __syncthreads();

    const int warp = tid >> 5, j = tid & 31;
    const int b = blockIdx.x * 8 + warp;
    if (b >= Bn) return;

    // ================= features FIRST (frees o-registers before GRU) ====
    float entropy, roc, corr;
    {
        const float* op = obs + (size_t)b * T_TOT * OBS_DIM;
        float o11[8], o12[8], o13[8], o14[8];
#pragma unroll
        for (int i = 0; i < 8; i++) {
            o11[i] = op[11 * OBS_DIM + i * 32 + j];
            o12[i] = op[12 * OBS_DIM + i * 32 + j];
            o13[i] = op[13 * OBS_DIM + i * 32 + j];
            o14[i] = op[14 * OBS_DIM + i * 32 + j];
        }

        float mx = o14[0];
#pragma unroll
        for (int i = 1; i < 8; i++) mx = fmaxf(mx, o14[i]);
        mx = wmax(mx);
        float s = 0.f;
#pragma unroll
        for (int i = 0; i < 8; i++) s += __expf(o14[i] - mx);
        s = wsum(s);
        float inv_s = 1.f / s;
        float es = 0.f;
#pragma unroll
        for (int i = 0; i < 8; i++) {
            float p = __expf(o14[i] - mx) * inv_s;
            es += p * __logf(p + 1e-8f);
        }
        es = wsum(es);
        entropy = -es;

        float d2a = 0.f, d2b = 0.f, d2c = 0.f;
#pragma unroll
        for (int i = 0; i < 8; i++) {
            float da = o12[i] - o11[i]; d2a = fmaf(da, da, d2a);
            float db = o13[i] - o12[i]; d2b = fmaf(db, db, d2b);
            float dc = o14[i] - o13[i]; d2c = fmaf(dc, dc, d2c);
        }
        d2a = wsum(d2a); d2b = wsum(d2b); d2c = wsum(d2c);
        roc = (sqrtf(d2a) + sqrtf(d2b) + sqrtf(d2c)) * (1.f / 3.f);

        float osum = 0.f;
#pragma unroll
        for (int i = 0; i < 8; i++) osum += o14[i];
        osum = wsum(osum);
        float om = osum * (1.f / 256.f);
        const float* ap = act + ((size_t)b * T_TOT + 13) * ACT_DIM;
        float a0 = ap[j], a1 = ap[32 + j];
        float am = wsum(a0 + a1) * (1.f / 256.f);
        float num = 0.f, do2 = 0.f;
#pragma unroll
        for (int i = 0; i < 8; i++) {
            float oc = o14[i] - om;
            do2 = fmaf(oc, oc, do2);
            float acv = ((i == 0) ? a0 : (i == 1) ? a1 : 0.f) - am;
            num = fmaf(oc, acv, num);
        }
        float da2 = (a0 - am) * (a0 - am) + (a1 - am) * (a1 - am) + 6.f * am * am;
        num = wsum(num); do2 = wsum(do2); da2 = wsum(da2);
        corr = num / (sqrtf(do2) * sqrtf(da2) + 1e-8f);
    }

    // ================= GRU (W_hh from smem) =============================
    const float bhr = bhh[j], bhz = bhh[32 + j], bhn = bhh[64 + j];
    const float* gip = g_GI + (size_t)b * NSTEP * NGATE;
    float gr = gip[j], gz = gip[32 + j], gn = gip[64 + j];
    float h = 0.f;
    float* myh = hs[warp];
    const float* wrj = whr[j];
    const float* wzj = whz[j];
    const float* wnj = whn[j];

#pragma unroll 1
    for (int t = 0; t < NSTEP; t++) {
        float ngr = 0.f, ngz = 0.f, ngn = 0.f;
        if (t + 1 < NSTEP) {
            const float* q = gip + (size_t)(t + 1) * NGATE;
            ngr = q[j]; ngz = q[32 + j]; ngn = q[64 + j];
        }
        myh[j] = h;
        __syncwarp();
        float ar0 = 0.f, az0 = 0.f, an0 = 0.f;
        float ar1 = 0.f, az1 = 0.f, an1 = 0.f;
#pragma unroll
        for (int k = 0; k < 16; k++) {
            float h0 = myh[k];
            float h1 = myh[16 + k];
            ar0 = fmaf(wrj[k], h0, ar0);
            az0 = fmaf(wzj[k], h0, az0);
            an0 = fmaf(wnj[k], h0, an0);
            ar1 = fmaf(wrj[16 + k], h1, ar1);
            az1 = fmaf(wzj[16 + k], h1, az1);
            an1 = fmaf(wnj[16 + k], h1, an1);
        }
        float ar = bhr + ar0 + ar1;
        float az = bhz + az0 + az1;
        float an = bhn + an0 + an1;
        float r = sigm(gr + ar);
        float z = sigm(gz + az);
        float n = tanh_fast(gn + r * an);
        __syncwarp();
        h = (1.f - z) * n + z * h;
        gr = ngr; gz = ngz; gn = ngn;
    }

    // ================= layernorm + MLP ==================================
    float* fb = wbuf[warp];
    if (j == 0) { fb[0] = entropy; fb[1] = roc; fb[2] = corr; }
    fb[3 + j] = h;
    __syncwarp();

    float v1 = fb[j];
    float v2 = (j < 3) ? fb[32 + j] : 0.f;
    float mu = wsum(v1 + v2) * (1.f / 35.f);
    float dd1 = v1 - mu;
    float dd2 = (j < 3) ? (v2 - mu) : 0.f;
    float var = wsum(dd1 * dd1 + dd2 * dd2) * (1.f / 35.f);
    float scl = rsqrtf(var + 1e-5f);
    __syncwarp();
    fb[j] = dd1 * scl * gms[j] + bts[j];
    if (j < 3) fb[32 + j] = dd2 * scl * gms[32 + j] + bts[32 + j];
    __syncwarp();

    float* fx1 = fb + 40;
    {
        float acc0 = b1s[j], acc1 = b1s[32 + j];
#pragma unroll
        for (int k = 0; k < 35; k++) {
            float f = fb[k];
            acc0 = fmaf(w1s[j * 35 + k], f, acc0);
            acc1 = fmaf(w1s[(32 + j) * 35 + k], f, acc1);
        }
        fx1[j] = fmaxf(acc0, 0.f);
        fx1[32 + j] = fmaxf(acc1, 0.f);
    }
    __syncwarp();

    float* fx2 = fb + 104;
    {
        float acc = b2s[j];
#pragma unroll
        for (int k = 0; k < 64; k++) acc = fmaf(w2s[j * 65 + k], fx1[k], acc);
        fx2[j] = fmaxf(acc, 0.f);
    }
    __syncwarp();

    float val = -INFINITY;
    if (j < 14) {
        float acc = b3s[j];
#pragma unroll
        for (int k = 0; k < 32; k++) acc = fmaf(w3s[j * 33 + k], fx2[k], acc);
        val = acc;
    }
    int idx = j;
#pragma unroll
    for (int off = 16; off; off >>= 1) {
        float ov = __shfl_down_sync(0xffffffffu, val, off);
        int oi = __shfl_down_sync(0xffffffffu, idx, off);
        if (ov > val || (ov == val && oi < idx)) { val = ov; idx = oi; }
    }
    idx = __shfl_sync(0xffffffffu, idx, 0);

    int wl = idx + 2;
    int s_off = (wl - 1) >> 1;
    int e_off = wl >> 1;

    if (j == 0) out[b] = (float)wl;
    if (j < MAXW) {
        int offp = j - 7;
        float mval = (offp >= -s_off && offp <= e_off) ? 1.f : 0.f;
        out[(size_t)Bn + (size_t)Bn * MAXW * KDIM + (size_t)b * MAXW + j] = mval;
    }

    // ---- padded window: 3 groups of 5 rows; loads batched before stores ----
    float* pw = out + Bn;
    const float4 z4 = make_float4(0.f, 0.f, 0.f, 0.f);
    const int lo_row = 7 - s_off, hi_row = 7 + e_off;
#pragma unroll
    for (int g = 0; g < 3; g++) {
        float4 va[5], vb[5], vc[5];
#pragma unroll
        for (int r = 0; r < 5; r++) {
            int o = g * 5 + r;
            bool on = (o >= lo_row) && (o <= hi_row);
            if (on) {
                const float4* so = (const float4*)(obs + (size_t)(b * T_TOT + 7 + o) * OBS_DIM);
                va[r] = so[j];
                vb[r] = so[32 + j];
                if (j < 16) {
                    const float4* sa = (const float4*)(act + (size_t)(b * T_TOT + 7 + o) * ACT_DIM);
                    vc[r] = sa[j];
                } else vc[r] = z4;
            } else {
                va[r] = z4; vb[r] = z4; vc[r] = z4;
            }
        }
#pragma unroll
        for (int r = 0; r < 5; r++) {
            int o = g * 5 + r;
            float4* dst = (float4*)(pw + ((size_t)b * MAXW + o) * KDIM);
            dst[j] = va[r];
            dst[32 + j] = vb[r];
            if (j < 16) dst[64 + j] = vc[r];
        }
    }
}

// =====================================================================
extern "C" void kernel_launch(void* const* d_in, const int* in_sizes, int n_in,
                              void* d_out, int out_size)
{
    const float* obs = (const float*)d_in[0];
    const float* act = (const float*)d_in[1];
    const float* Wih = (const float*)d_in[2];
    const float* Whh = (const float*)d_in[3];
    const float* bih = (const float*)d_in[4];
    const float* bhh = (const float*)d_in[5];
    const float* lng = (const float*)d_in[6];
    const float* lnb = (const float*)d_in[7];
    const float* W1  = (const float*)d_in[8];
    const float* b1  = (const float*)d_in[9];
    const float* W2  = (const float*)d_in[10];
    const float* b2  = (const float*)d_in[11];
    const float* W3  = (const float*)d_in[12];
    const float* b3  = (const float*)d_in[13];

    int Bn = in_sizes[0] / (T_TOT * OBS_DIM);
    if (Bn > MAXB) Bn = MAXB;
    float* out = (float*)d_out;

    int Mtot = Bn * NSTEP;
    int gemm_blocks = (Mtot + BM - 1) / BM;
    k_gemm<<<gemm_blocks, 128>>>(obs, act, Wih, bih, Bn);

    int fused_blocks = (Bn + 7) / 8;
    k_fused<<<fused_blocks, 256>>>(obs, act, Whh, bhh, lng, lnb,
                                   W1, b1, W2, b2, W3, b3, out, Bn);
}

// round 10
// speedup vs baseline: 1.1060x; 1.1060x over previous
#include <cuda_runtime.h>
#include <math.h>
#include <stdint.h>

#define OBS_DIM 256
#define ACT_DIM 64
#define T_TOT   22
#define HID     32
#define MAXW    15
#define NSTEP   15
#define NGATE   96
#define KDIM    320
#define MAXB    8192

// GRU pre-activation scratch: GI[(b*15+t)*96 + g]
__device__ float g_GI[(size_t)MAXB * NSTEP * NGATE];
// W_ih split into tf32 hi/lo, transposed to k-major [320][96]
__device__ __align__(16) float g_Whi[KDIM * NGATE];
__device__ __align__(16) float g_Wlo[KDIM * NGATE];

__device__ __forceinline__ uint32_t tf32hi_bits(float x) {
    uint32_t h;
    asm("cvt.rna.tf32.f32 %0, %1;" : "=r"(h) : "f"(x));
    return h;
}

__device__ __forceinline__ void mma_tf32(float* c, uint32_t a0, uint32_t a1,
                                         uint32_t a2, uint32_t a3,
                                         uint32_t b0, uint32_t b1) {
    asm volatile(
        "mma.sync.aligned.m16n8k8.row.col.f32.tf32.tf32.f32 "
        "{%0,%1,%2,%3}, {%4,%5,%6,%7}, {%8,%9}, {%0,%1,%2,%3};\n"
        : "+f"(c[0]), "+f"(c[1]), "+f"(c[2]), "+f"(c[3])
        : "r"(a0), "r"(a1), "r"(a2), "r"(a3), "r"(b0), "r"(b1));
}

__device__ __forceinline__ float wsum(float x) {
#pragma unroll
    for (int o = 16; o; o >>= 1) x += __shfl_xor_sync(0xffffffffu, x, o);
    return x;
}
__device__ __forceinline__ float wmax(float x) {
#pragma unroll
    for (int o = 16; o; o >>= 1) x = fmaxf(x, __shfl_xor_sync(0xffffffffu, x, o));
    return x;
}
__device__ __forceinline__ float sigm(float x) { return 1.f / (1.f + __expf(-x)); }
__device__ __forceinline__ float tanh_fast(float x) {
    float e = __expf(-2.f * fabsf(x));
    float r = (1.f - e) / (1.f + e);
    return copysignf(r, x);
}

// =====================================================================
// Kernel 0: split W_ih [96][320] into tf32 hi/lo, k-major [320][96]
// =====================================================================
__global__ void k_wprep(const float* __restrict__ Wih) {
    int i = blockIdx.x * 256 + threadIdx.x;
    if (i < KDIM * NGATE) {
        int k = i / NGATE, n = i - k * NGATE;
        float x = Wih[(size_t)n * KDIM + k];
        float hi = __uint_as_float(tf32hi_bits(x));
        g_Whi[i] = hi;
        g_Wlo[i] = x - hi;
    }
}

// =====================================================================
// Kernel 1: tensor-core GEMM. GI[M=Bn*15,96] = X[M,320] @ W^T + b
// mma.sync.m16n8k8 tf32, 3-pass split. CTA: 128 thr, tile 64m x 96n.
// =====================================================================
#define XSTR 36
#define WSTR 104

__global__ __launch_bounds__(128) void k_gemm_mma(
    const float* __restrict__ obs, const float* __restrict__ act,
    const float* __restrict__ bih, int Bn)
{
    __shared__ float Xhi[64][XSTR], Xlo[64][XSTR];
    __shared__ float Whs[32][WSTR], Wls[32][WSTR];
    __shared__ float sbias[96];

    const int tid = threadIdx.x;
    const int warp = tid >> 5, lane = tid & 31;
    const int Mtot = Bn * NSTEP;
    const int m_base = blockIdx.x * 64;

    if (tid < 96) sbias[tid] = bih[tid];

    // per-thread X-load rows (same every k-tile): 4 rows
    int rowptr[4];
#pragma unroll
    for (int i = 0; i < 4; i++) {
        int idx = i * 128 + tid;
        int r = idx >> 3;
        int gm = m_base + r;
        int gmc = gm < Mtot ? gm : Mtot - 1;
        int bb = gmc / NSTEP;
        int tt = gmc - bb * NSTEP;
        rowptr[i] = bb * T_TOT + tt;
    }
    const int c4 = tid & 7;

    float acc[12][4];
#pragma unroll
    for (int nt = 0; nt < 12; nt++)
#pragma unroll
        for (int q = 0; q < 4; q++) acc[nt][q] = 0.f;

    const int ar = lane >> 2, ac = lane & 3;
    const int brow = lane & 3, bcol = lane >> 2;

#pragma unroll 1
    for (int kt = 0; kt < 10; kt++) {
        const int k0 = kt * 32;
        // ---- X tile: 64 rows x 32 cols, split hi/lo ----
#pragma unroll
        for (int i = 0; i < 4; i++) {
            int idx = i * 128 + tid;
            int r = idx >> 3;
            int kk = k0 + c4 * 4;
            const float* src = (k0 < OBS_DIM)
                ? obs + (size_t)rowptr[i] * OBS_DIM + kk
                : act + (size_t)rowptr[i] * ACT_DIM + (kk - OBS_DIM);
            float4 v = *(const float4*)src;
            float4 h, l;
            h.x = __uint_as_float(tf32hi_bits(v.x)); l.x = v.x - h.x;
            h.y = __uint_as_float(tf32hi_bits(v.y)); l.y = v.y - h.y;
            h.z = __uint_as_float(tf32hi_bits(v.z)); l.z = v.z - h.z;
            h.w = __uint_as_float(tf32hi_bits(v.w)); l.w = v.w - h.w;
            *(float4*)&Xhi[r][c4 * 4] = h;
            *(float4*)&Xlo[r][c4 * 4] = l;
        }
        // ---- W tile: pre-split k-major [32][96] -> smem ----
#pragma unroll
        for (int i = 0; i < 6; i++) {
            int idx = i * 128 + tid;            // 0..767 float4s
            int k = idx / 24, n4 = idx - k * 24;
            size_t goff = (size_t)(k0 + k) * NGATE + n4 * 4;
            float4 h = *(const float4*)(g_Whi + goff);
            float4 l = *(const float4*)(g_Wlo + goff);
            *(float4*)&Whs[k][n4 * 4] = h;
            *(float4*)&Wls[k][n4 * 4] = l;
        }
        __syncthreads();

        // ---- 4 k-steps of 8 ----
#pragma unroll
        for (int ks = 0; ks < 4; ks++) {
            const int kk = ks * 8;
            const int m0 = warp * 16;
            uint32_t ah0 = __float_as_uint(Xhi[m0 + ar][kk + ac]);
            uint32_t ah1 = __float_as_uint(Xhi[m0 + ar + 8][kk + ac]);
            uint32_t ah2 = __float_as_uint(Xhi[m0 + ar][kk + ac + 4]);
            uint32_t ah3 = __float_as_uint(Xhi[m0 + ar + 8][kk + ac + 4]);
            uint32_t al0 = __float_as_uint(Xlo[m0 + ar][kk + ac]);
            uint32_t al1 = __float_as_uint(Xlo[m0 + ar + 8][kk + ac]);
            uint32_t al2 = __float_as_uint(Xlo[m0 + ar][kk + ac + 4]);
            uint32_t al3 = __float_as_uint(Xlo[m0 + ar + 8][kk + ac + 4]);
#pragma unroll
            for (int nt = 0; nt < 12; nt++) {
                int bn = nt * 8 + bcol;
                uint32_t bh0 = __float_as_uint(Whs[kk + brow][bn]);
                uint32_t bh1 = __float_as_uint(Whs[kk + brow + 4][bn]);
                uint32_t bl0 = __float_as_uint(Wls[kk + brow][bn]);
                uint32_t bl1 = __float_as_uint(Wls[kk + brow + 4][bn]);
                mma_tf32(acc[nt], ah0, ah1, ah2, ah3, bh0, bh1);
                mma_tf32(acc[nt], ah0, ah1, ah2, ah3, bl0, bl1);
                mma_tf32(acc[nt], al0, al1, al2, al3, bh0, bh1);
            }
        }
        __syncthreads();
    }

    // ---- epilogue: C fragments -> GI with bias ----
    const int r0 = m_base + warp * 16 + (lane >> 2);
    const int r1 = r0 + 8;
#pragma unroll
    for (int nt = 0; nt < 12; nt++) {
        int cc = nt * 8 + 2 * (lane & 3);
        float bx = sbias[cc], by = sbias[cc + 1];
        if (r0 < Mtot) {
            float2 o = make_float2(acc[nt][0] + bx, acc[nt][1] + by);
            *(float2*)(g_GI + (size_t)r0 * NGATE + cc) = o;
        }
        if (r1 < Mtot) {
            float2 o = make_float2(acc[nt][2] + bx, acc[nt][3] + by);
            *(float2*)(g_GI + (size_t)r1 * NGATE + cc) = o;
        }
    }
}

// =====================================================================
// Kernel 2 (fused, R9 known-good 96.5us): features first, W_hh in smem,
// GRU + LN + MLP + argmax + mask + grouped window.
// =====================================================================
__global__ __launch_bounds__(256, 3) void k_fused(
    const float* __restrict__ obs, const float* __restrict__ act,
    const float* __restrict__ Whh, const float* __restrict__ bhh,
    const float* __restrict__ lng, const float* __restrict__ lnb,
    const float* __restrict__ W1, const float* __restrict__ b1,
    const float* __restrict__ W2, const float* __restrict__ b2,
    const float* __restrict__ W3, const float* __restrict__ b3,
    float* __restrict__ out, int Bn)
{
    __shared__ float whr[32][33], whz[32][33], whn[32][33];
    __shared__ float w1s[64 * 35];
    __shared__ float w2s[32 * 65];
    __shared__ float w3s[14 * 33];
    __shared__ float b1s[64], b2s[32], b3s[14];
    __shared__ float gms[35], bts[35];
    __shared__ float wbuf[8][144];
    __shared__ float hs[8][32];

    const int tid = threadIdx.x;
    for (int i = tid; i < 3 * HID * HID; i += 256) {
        int row = i >> 5, k = i & 31;
        float v = Whh[i];
        if (row < 32)       whr[row][k] = v;
        else if (row < 64)  whz[row - 32][k] = v;
        else                whn[row - 64][k] = v;
    }
    for (int i = tid; i < 64 * 35; i += 256) w1s[i] = W1[i];
    for (int i = tid; i < 32 * 64; i += 256) w2s[(i >> 6) * 65 + (i & 63)] = W2[i];
    for (int i = tid; i < 14 * 32; i += 256) w3s[(i >> 5) * 33 + (i & 31)] = W3[i];
    if (tid < 64) b1s[tid] = b1[tid];
    if (tid < 32) b2s[tid] = b2[tid];
    if (tid < 14) b3s[tid] = b3[tid];
    if (tid < 35) { gms[tid] = lng[tid]; bts[tid] = lnb[tid]; }
    __syncthreads();

    const int warp = tid >> 5, j = tid & 31;
    const int b = blockIdx.x * 8 + warp;
    if (b >= Bn) return;

    // ================= features FIRST ===================================
    float entropy, roc, corr;
    {
        const float* op = obs + (size_t)b * T_TOT * OBS_DIM;
        float o11[8], o12[8], o13[8], o14[8];
#pragma unroll
        for (int i = 0; i < 8; i++) {
            o11[i] = op[11 * OBS_DIM + i * 32 + j];
            o12[i] = op[12 * OBS_DIM + i * 32 + j];
            o13[i] = op[13 * OBS_DIM + i * 32 + j];
            o14[i] = op[14 * OBS_DIM + i * 32 + j];
        }

        float mx = o14[0];
#pragma unroll
        for (int i = 1; i < 8; i++) mx = fmaxf(mx, o14[i]);
        mx = wmax(mx);
        float s = 0.f;
#pragma unroll
        for (int i = 0; i < 8; i++) s += __expf(o14[i] - mx);
        s = wsum(s);
        float inv_s = 1.f / s;
        float es = 0.f;
#pragma unroll
        for (int i = 0; i < 8; i++) {
            float p = __expf(o14[i] - mx) * inv_s;
            es += p * __logf(p + 1e-8f);
        }
        es = wsum(es);
        entropy = -es;

        float d2a = 0.f, d2b = 0.f, d2c = 0.f;
#pragma unroll
        for (int i = 0; i < 8; i++) {
            float da = o12[i] - o11[i]; d2a = fmaf(da, da, d2a);
            float db = o13[i] - o12[i]; d2b = fmaf(db, db, d2b);
            float dc = o14[i] - o13[i]; d2c = fmaf(dc, dc, d2c);
        }
        d2a = wsum(d2a); d2b = wsum(d2b); d2c = wsum(d2c);
        roc = (sqrtf(d2a) + sqrtf(d2b) + sqrtf(d2c)) * (1.f / 3.f);

        float osum = 0.f;
#pragma unroll
        for (int i = 0; i < 8; i++) osum += o14[i];
        osum = wsum(osum);
        float om = osum * (1.f / 256.f);
        const float* ap = act + ((size_t)b * T_TOT + 13) * ACT_DIM;
        float a0 = ap[j], a1 = ap[32 + j];
        float am = wsum(a0 + a1) * (1.f / 256.f);
        float num = 0.f, do2 = 0.f;
#pragma unroll
        for (int i = 0; i < 8; i++) {
            float oc = o14[i] - om;
            do2 = fmaf(oc, oc, do2);
            float acv = ((i == 0) ? a0 : (i == 1) ? a1 : 0.f) - am;
            num = fmaf(oc, acv, num);
        }
        float da2 = (a0 - am) * (a0 - am) + (a1 - am) * (a1 - am) + 6.f * am * am;
        num = wsum(num); do2 = wsum(do2); da2 = wsum(da2);
        corr = num / (sqrtf(do2) * sqrtf(da2) + 1e-8f);
    }

    // ================= GRU (W_hh from smem) =============================
    const float bhr = bhh[j], bhz = bhh[32 + j], bhn = bhh[64 + j];
    const float* gip = g_GI + (size_t)b * NSTEP * NGATE;
    float gr = gip[j], gz = gip[32 + j], gn = gip[64 + j];
    float h = 0.f;
    float* myh = hs[warp];
    const float* wrj = whr[j];
    const float* wzj = whz[j];
    const float* wnj = whn[j];

#pragma unroll 1
    for (int t = 0; t < NSTEP; t++) {
        float ngr = 0.f, ngz = 0.f, ngn = 0.f;
        if (t + 1 < NSTEP) {
            const float* q = gip + (size_t)(t + 1) * NGATE;
            ngr = q[j]; ngz = q[32 + j]; ngn = q[64 + j];
        }
        myh[j] = h;
        __syncwarp();
        float ar0 = 0.f, az0 = 0.f, an0 = 0.f;
        float ar1 = 0.f, az1 = 0.f, an1 = 0.f;
#pragma unroll
        for (int k = 0; k < 16; k++) {
            float h0 = myh[k];
            float h1 = myh[16 + k];
            ar0 = fmaf(wrj[k], h0, ar0);
            az0 = fmaf(wzj[k], h0, az0);
            an0 = fmaf(wnj[k], h0, an0);
            ar1 = fmaf(wrj[16 + k], h1, ar1);
            az1 = fmaf(wzj[16 + k], h1, az1);
            an1 = fmaf(wnj[16 + k], h1, an1);
        }
        float ar = bhr + ar0 + ar1;
        float az = bhz + az0 + az1;
        float an = bhn + an0 + an1;
        float r = sigm(gr + ar);
        float z = sigm(gz + az);
        float n = tanh_fast(gn + r * an);
        __syncwarp();
        h = (1.f - z) * n + z * h;
        gr = ngr; gz = ngz; gn = ngn;
    }

    // ================= layernorm + MLP ==================================
    float* fb = wbuf[warp];
    if (j == 0) { fb[0] = entropy; fb[1] = roc; fb[2] = corr; }
    fb[3 + j] = h;
    __syncwarp();

    float v1 = fb[j];
    float v2 = (j < 3) ? fb[32 + j] : 0.f;
    float mu = wsum(v1 + v2) * (1.f / 35.f);
    float dd1 = v1 - mu;
    float dd2 = (j < 3) ? (v2 - mu) : 0.f;
    float var = wsum(dd1 * dd1 + dd2 * dd2) * (1.f / 35.f);
    float scl = rsqrtf(var + 1e-5f);
    __syncwarp();
    fb[j] = dd1 * scl * gms[j] + bts[j];
    if (j < 3) fb[32 + j] = dd2 * scl * gms[32 + j] + bts[32 + j];
    __syncwarp();

    float* fx1 = fb + 40;
    {
        float acc0 = b1s[j], acc1 = b1s[32 + j];
#pragma unroll
        for (int k = 0; k < 35; k++) {
            float f = fb[k];
            acc0 = fmaf(w1s[j * 35 + k], f, acc0);
            acc1 = fmaf(w1s[(32 + j) * 35 + k], f, acc1);
        }
        fx1[j] = fmaxf(acc0, 0.f);
        fx1[32 + j] = fmaxf(acc1, 0.f);
    }
    __syncwarp();

    float* fx2 = fb + 104;
    {
        float acc = b2s[j];
#pragma unroll
        for (int k = 0; k < 64; k++) acc = fmaf(w2s[j * 65 + k], fx1[k], acc);
        fx2[j] = fmaxf(acc, 0.f);
    }
    __syncwarp();

    float val = -INFINITY;
    if (j < 14) {
        float acc = b3s[j];
#pragma unroll
        for (int k = 0; k < 32; k++) acc = fmaf(w3s[j * 33 + k], fx2[k], acc);
        val = acc;
    }
    int idx = j;
#pragma unroll
    for (int off = 16; off; off >>= 1) {
        float ov = __shfl_down_sync(0xffffffffu, val, off);
        int oi = __shfl_down_sync(0xffffffffu, idx, off);
        if (ov > val || (ov == val && oi < idx)) { val = ov; idx = oi; }
    }
    idx = __shfl_sync(0xffffffffu, idx, 0);

    int wl = idx + 2;
    int s_off = (wl - 1) >> 1;
    int e_off = wl >> 1;

    if (j == 0) out[b] = (float)wl;
    if (j < MAXW) {
        int offp = j - 7;
        float mval = (offp >= -s_off && offp <= e_off) ? 1.f : 0.f;
        out[(size_t)Bn + (size_t)Bn * MAXW * KDIM + (size_t)b * MAXW + j] = mval;
    }

    // ---- padded window: 3 groups of 5 rows ----
    float* pw = out + Bn;
    const float4 z4 = make_float4(0.f, 0.f, 0.f, 0.f);
    const int lo_row = 7 - s_off, hi_row = 7 + e_off;
#pragma unroll
    for (int g = 0; g < 3; g++) {
        float4 va[5], vb[5], vc[5];
#pragma unroll
        for (int r = 0; r < 5; r++) {
            int o = g * 5 + r;
            bool on = (o >= lo_row) && (o <= hi_row);
            if (on) {
                const float4* so = (const float4*)(obs + (size_t)(b * T_TOT + 7 + o) * OBS_DIM);
                va[r] = so[j];
                vb[r] = so[32 + j];
                if (j < 16) {
                    const float4* sa = (const float4*)(act + (size_t)(b * T_TOT + 7 + o) * ACT_DIM);
                    vc[r] = sa[j];
                } else vc[r] = z4;
            } else {
                va[r] = z4; vb[r] = z4; vc[r] = z4;
            }
        }
#pragma unroll
        for (int r = 0; r < 5; r++) {
            int o = g * 5 + r;
            float4* dst = (float4*)(pw + ((size_t)b * MAXW + o) * KDIM);
            dst[j] = va[r];
            dst[32 + j] = vb[r];
            if (j < 16) dst[64 + j] = vc[r];
        }
    }
}

// =====================================================================
extern "C" void kernel_launch(void* const* d_in, const int* in_sizes, int n_in,
                              void* d_out, int out_size)
{
    const float* obs = (const float*)d_in[0];
    const float* act = (const float*)d_in[1];
    const float* Wih = (const float*)d_in[2];
    const float* Whh = (const float*)d_in[3];
    const float* bih = (const float*)d_in[4];
    const float* bhh = (const float*)d_in[5];
    const float* lng = (const float*)d_in[6];
    const float* lnb = (const float*)d_in[7];
    const float* W1  = (const float*)d_in[8];
    const float* b1  = (const float*)d_in[9];
    const float* W2  = (const float*)d_in[10];
    const float* b2  = (const float*)d_in[11];
    const float* W3  = (const float*)d_in[12];
    const float* b3  = (const float*)d_in[13];

    int Bn = in_sizes[0] / (T_TOT * OBS_DIM);
    if (Bn > MAXB) Bn = MAXB;
    float* out = (float*)d_out;

    k_wprep<<<(KDIM * NGATE + 255) / 256, 256>>>(Wih);

    int Mtot = Bn * NSTEP;
    int gemm_blocks = (Mtot + 63) / 64;
    k_gemm_mma<<<gemm_blocks, 128>>>(obs, act, bih, Bn);

    int fused_blocks = (Bn + 7) / 8;
    k_fused<<<fused_blocks, 256>>>(obs, act, Whh, bhh, lng, lnb,
                                   W1, b1, W2, b2, W3, b3, out, Bn);
}

// round 11
// speedup vs baseline: 1.1425x; 1.0330x over previous
#include <cuda_runtime.h>
#include <math.h>
#include <stdint.h>

#define OBS_DIM 256
#define ACT_DIM 64
#define T_TOT   22
#define HID     32
#define MAXW    15
#define NSTEP   15
#define NGATE   96
#define KDIM    320
#define MAXB    8192

// GRU pre-activation scratch: GI[(b*15+t)*96 + g]
__device__ float g_GI[(size_t)MAXB * NSTEP * NGATE];
// W_ih fragment-packed: [kt(10)][ks(4)][bn(96)][brow(4)] float4{bh0,bh1,bl0,bl1}
__device__ __align__(16) float4 g_Wp[10 * 4 * NGATE * 4];

__device__ __forceinline__ uint32_t tf32hi_bits(float x) {
    uint32_t h;
    asm("cvt.rna.tf32.f32 %0, %1;" : "=r"(h) : "f"(x));
    return h;
}

__device__ __forceinline__ void mma_tf32(float* c, uint32_t a0, uint32_t a1,
                                         uint32_t a2, uint32_t a3,
                                         uint32_t b0, uint32_t b1) {
    asm volatile(
        "mma.sync.aligned.m16n8k8.row.col.f32.tf32.tf32.f32 "
        "{%0,%1,%2,%3}, {%4,%5,%6,%7}, {%8,%9}, {%0,%1,%2,%3};\n"
        : "+f"(c[0]), "+f"(c[1]), "+f"(c[2]), "+f"(c[3])
        : "r"(a0), "r"(a1), "r"(a2), "r"(a3), "r"(b0), "r"(b1));
}

__device__ __forceinline__ float wsum(float x) {
#pragma unroll
    for (int o = 16; o; o >>= 1) x += __shfl_xor_sync(0xffffffffu, x, o);
    return x;
}
__device__ __forceinline__ float wmax(float x) {
#pragma unroll
    for (int o = 16; o; o >>= 1) x = fmaxf(x, __shfl_xor_sync(0xffffffffu, x, o));
    return x;
}
__device__ __forceinline__ float sigm(float x) { return 1.f / (1.f + __expf(-x)); }
__device__ __forceinline__ float tanh_fast(float x) {
    float e = __expf(-2.f * fabsf(x));
    float r = (1.f - e) / (1.f + e);
    return copysignf(r, x);
}

// =====================================================================
// Kernel 0: pack W_ih into fragment-ready tf32 hi/lo quads.
// p -> (kt*4+ks, bn, brow): k = (kt*4+ks)*8 + brow
// float4 = { hi(k,bn), hi(k+4,bn), lo(k,bn), lo(k+4,bn) }
// =====================================================================
__global__ void k_wprep(const float* __restrict__ Wih) {
    int p = blockIdx.x * 256 + threadIdx.x;
    if (p >= 10 * 4 * NGATE * 4) return;
    int brow = p & 3;
    int t = p >> 2;
    int bn = t % NGATE;
    int kk8 = t / NGATE;              // 0..39
    int k = kk8 * 8 + brow;
    float x0 = Wih[(size_t)bn * KDIM + k];
    float x1 = Wih[(size_t)bn * KDIM + k + 4];
    float h0 = __uint_as_float(tf32hi_bits(x0));
    float h1 = __uint_as_float(tf32hi_bits(x1));
    g_Wp[p] = make_float4(h0, h1, x0 - h0, x1 - h1);
}

// =====================================================================
// Kernel 1: tensor-core GEMM. GI[M=Bn*15,96] = X[M,320] @ W^T + b
// mma.sync.m16n8k8 tf32 3-pass. CTA: 128 thr, tile 128m x 96n,
// warp tile 32m x 96n. W fragments via single LDS.128.
// =====================================================================
#define XSTR 36
#define XTILE (128 * XSTR)                 // floats per X buffer
#define WTILE (4 * NGATE * 4)              // float4s per W k-tile (1536)
#define GEMM_SMEM_BYTES (2 * XTILE * 4 + WTILE * 16)

__global__ __launch_bounds__(128) void k_gemm_mma(
    const float* __restrict__ obs, const float* __restrict__ act,
    const float* __restrict__ bih, int Bn)
{
    extern __shared__ float smem[];
    float* Xhi = smem;                         // [128][XSTR]
    float* Xlo = smem + XTILE;                 // [128][XSTR]
    float4* Wp = (float4*)(smem + 2 * XTILE);  // [4][96][4] float4
    __shared__ float sbias[96];

    const int tid = threadIdx.x;
    const int warp = tid >> 5, lane = tid & 31;
    const int Mtot = Bn * NSTEP;
    const int m_base = blockIdx.x * 128;

    if (tid < 96) sbias[tid] = bih[tid];

    // per-thread X-load row indices (8 rows, fixed across k-tiles)
    int rowptr[8];
#pragma unroll
    for (int i = 0; i < 8; i++) {
        int idx = i * 128 + tid;
        int r = idx >> 3;
        int gm = m_base + r;
        int gmc = gm < Mtot ? gm : Mtot - 1;
        int bb = gmc / NSTEP;
        int tt = gmc - bb * NSTEP;
        rowptr[i] = bb * T_TOT + tt;
    }
    const int c4 = tid & 7;

    float acc[2][12][4];
#pragma unroll
    for (int mt = 0; mt < 2; mt++)
#pragma unroll
        for (int nt = 0; nt < 12; nt++)
#pragma unroll
            for (int q = 0; q < 4; q++) acc[mt][nt][q] = 0.f;

    const int ar = lane >> 2, ac = lane & 3;
    const int brow = lane & 3, bcol = lane >> 2;
    const int m0 = warp * 32;

#pragma unroll 1
    for (int kt = 0; kt < 10; kt++) {
        const int k0 = kt * 32;
        // ---- X tile: 128 rows x 32 cols, split hi/lo ----
#pragma unroll
        for (int i = 0; i < 8; i++) {
            int idx = i * 128 + tid;
            int r = idx >> 3;
            int kk = k0 + c4 * 4;
            const float* src = (k0 < OBS_DIM)
                ? obs + (size_t)rowptr[i] * OBS_DIM + kk
                : act + (size_t)rowptr[i] * ACT_DIM + (kk - OBS_DIM);
            float4 v = *(const float4*)src;
            float4 h, l;
            h.x = __uint_as_float(tf32hi_bits(v.x)); l.x = v.x - h.x;
            h.y = __uint_as_float(tf32hi_bits(v.y)); l.y = v.y - h.y;
            h.z = __uint_as_float(tf32hi_bits(v.z)); l.z = v.z - h.z;
            h.w = __uint_as_float(tf32hi_bits(v.w)); l.w = v.w - h.w;
            *(float4*)&Xhi[r * XSTR + c4 * 4] = h;
            *(float4*)&Xlo[r * XSTR + c4 * 4] = l;
        }
        // ---- W tile: packed fragments, contiguous copy ----
        {
            const float4* gW = g_Wp + (size_t)kt * WTILE;
#pragma unroll
            for (int i = 0; i < 12; i++) {
                int idx = i * 128 + tid;
                Wp[idx] = gW[idx];
            }
        }
        __syncthreads();

        // ---- 4 k-steps of 8 ----
#pragma unroll
        for (int ks = 0; ks < 4; ks++) {
            const int kk = ks * 8;
            // A fragments for both 16m sub-tiles (hi & lo)
            uint32_t ah[2][4], al[2][4];
#pragma unroll
            for (int mt = 0; mt < 2; mt++) {
                int mr = m0 + mt * 16 + ar;
                ah[mt][0] = __float_as_uint(Xhi[mr * XSTR + kk + ac]);
                ah[mt][1] = __float_as_uint(Xhi[(mr + 8) * XSTR + kk + ac]);
                ah[mt][2] = __float_as_uint(Xhi[mr * XSTR + kk + ac + 4]);
                ah[mt][3] = __float_as_uint(Xhi[(mr + 8) * XSTR + kk + ac + 4]);
                al[mt][0] = __float_as_uint(Xlo[mr * XSTR + kk + ac]);
                al[mt][1] = __float_as_uint(Xlo[(mr + 8) * XSTR + kk + ac]);
                al[mt][2] = __float_as_uint(Xlo[mr * XSTR + kk + ac + 4]);
                al[mt][3] = __float_as_uint(Xlo[(mr + 8) * XSTR + kk + ac + 4]);
            }
            const float4* wrow = Wp + ks * (NGATE * 4);
#pragma unroll
            for (int nt = 0; nt < 12; nt++) {
                float4 bf = wrow[(nt * 8 + bcol) * 4 + brow];
                uint32_t bh0 = __float_as_uint(bf.x);
                uint32_t bh1 = __float_as_uint(bf.y);
                uint32_t bl0 = __float_as_uint(bf.z);
                uint32_t bl1 = __float_as_uint(bf.w);
#pragma unroll
                for (int mt = 0; mt < 2; mt++) {
                    mma_tf32(acc[mt][nt], ah[mt][0], ah[mt][1], ah[mt][2], ah[mt][3], bh0, bh1);
                    mma_tf32(acc[mt][nt], ah[mt][0], ah[mt][1], ah[mt][2], ah[mt][3], bl0, bl1);
                    mma_tf32(acc[mt][nt], al[mt][0], al[mt][1], al[mt][2], al[mt][3], bh0, bh1);
                }
            }
        }
        __syncthreads();
    }

    // ---- epilogue: C fragments -> GI with bias ----
#pragma unroll
    for (int mt = 0; mt < 2; mt++) {
        const int r0 = m_base + m0 + mt * 16 + (lane >> 2);
        const int r1 = r0 + 8;
#pragma unroll
        for (int nt = 0; nt < 12; nt++) {
            int cc = nt * 8 + 2 * (lane & 3);
            float bx = sbias[cc], by = sbias[cc + 1];
            if (r0 < Mtot) {
                float2 o = make_float2(acc[mt][nt][0] + bx, acc[mt][nt][1] + by);
                *(float2*)(g_GI + (size_t)r0 * NGATE + cc) = o;
            }
            if (r1 < Mtot) {
                float2 o = make_float2(acc[mt][nt][2] + bx, acc[mt][nt][3] + by);
                *(float2*)(g_GI + (size_t)r1 * NGATE + cc) = o;
            }
        }
    }
}

// =====================================================================
// Kernel 2 (fused, R9 known-good 96.5us)
// =====================================================================
__global__ __launch_bounds__(256, 3) void k_fused(
    const float* __restrict__ obs, const float* __restrict__ act,
    const float* __restrict__ Whh, const float* __restrict__ bhh,
    const float* __restrict__ lng, const float* __restrict__ lnb,
    const float* __restrict__ W1, const float* __restrict__ b1,
    const float* __restrict__ W2, const float* __restrict__ b2,
    const float* __restrict__ W3, const float* __restrict__ b3,
    float* __restrict__ out, int Bn)
{
    __shared__ float whr[32][33], whz[32][33], whn[32][33];
    __shared__ float w1s[64 * 35];
    __shared__ float w2s[32 * 65];
    __shared__ float w3s[14 * 33];
    __shared__ float b1s[64], b2s[32], b3s[14];
    __shared__ float gms[35], bts[35];
    __shared__ float wbuf[8][144];
    __shared__ float hs[8][32];

    const int tid = threadIdx.x;
    for (int i = tid; i < 3 * HID * HID; i += 256) {
        int row = i >> 5, k = i & 31;
        float v = Whh[i];
        if (row < 32)       whr[row][k] = v;
        else if (row < 64)  whz[row - 32][k] = v;
        else                whn[row - 64][k] = v;
    }
    for (int i = tid; i < 64 * 35; i += 256) w1s[i] = W1[i];
    for (int i = tid; i < 32 * 64; i += 256) w2s[(i >> 6) * 65 + (i & 63)] = W2[i];
    for (int i = tid; i < 14 * 32; i += 256) w3s[(i >> 5) * 33 + (i & 31)] = W3[i];
    if (tid < 64) b1s[tid] = b1[tid];
    if (tid < 32) b2s[tid] = b2[tid];
    if (tid < 14) b3s[tid] = b3[tid];
    if (tid < 35) { gms[tid] = lng[tid]; bts[tid] = lnb[tid]; }
    __syncthreads();

    const int warp = tid >> 5, j = tid & 31;
    const int b = blockIdx.x * 8 + warp;
    if (b >= Bn) return;

    // ================= features FIRST ===================================
    float entropy, roc, corr;
    {
        const float* op = obs + (size_t)b * T_TOT * OBS_DIM;
        float o11[8], o12[8], o13[8], o14[8];
#pragma unroll
        for (int i = 0; i < 8; i++) {
            o11[i] = op[11 * OBS_DIM + i * 32 + j];
            o12[i] = op[12 * OBS_DIM + i * 32 + j];
            o13[i] = op[13 * OBS_DIM + i * 32 + j];
            o14[i] = op[14 * OBS_DIM + i * 32 + j];
        }

        float mx = o14[0];
#pragma unroll
        for (int i = 1; i < 8; i++) mx = fmaxf(mx, o14[i]);
        mx = wmax(mx);
        float s = 0.f;
#pragma unroll
        for (int i = 0; i < 8; i++) s += __expf(o14[i] - mx);
        s = wsum(s);
        float inv_s = 1.f / s;
        float es = 0.f;
#pragma unroll
        for (int i = 0; i < 8; i++) {
            float p = __expf(o14[i] - mx) * inv_s;
            es += p * __logf(p + 1e-8f);
        }
        es = wsum(es);
        entropy = -es;

        float d2a = 0.f, d2b = 0.f, d2c = 0.f;
#pragma unroll
        for (int i = 0; i < 8; i++) {
            float da = o12[i] - o11[i]; d2a = fmaf(da, da, d2a);
            float db = o13[i] - o12[i]; d2b = fmaf(db, db, d2b);
            float dc = o14[i] - o13[i]; d2c = fmaf(dc, dc, d2c);
        }
        d2a = wsum(d2a); d2b = wsum(d2b); d2c = wsum(d2c);
        roc = (sqrtf(d2a) + sqrtf(d2b) + sqrtf(d2c)) * (1.f / 3.f);

        float osum = 0.f;
#pragma unroll
        for (int i = 0; i < 8; i++) osum += o14[i];
        osum = wsum(osum);
        float om = osum * (1.f / 256.f);
        const float* ap = act + ((size_t)b * T_TOT + 13) * ACT_DIM;
        float a0 = ap[j], a1 = ap[32 + j];
        float am = wsum(a0 + a1) * (1.f / 256.f);
        float num = 0.f, do2 = 0.f;
#pragma unroll
        for (int i = 0; i < 8; i++) {
            float oc = o14[i] - om;
            do2 = fmaf(oc, oc, do2);
            float acv = ((i == 0) ? a0 : (i == 1) ? a1 : 0.f) - am;
            num = fmaf(oc, acv, num);
        }
        float da2 = (a0 - am) * (a0 - am) + (a1 - am) * (a1 - am) + 6.f * am * am;
        num = wsum(num); do2 = wsum(do2); da2 = wsum(da2);
        corr = num / (sqrtf(do2) * sqrtf(da2) + 1e-8f);
    }

    // ================= GRU (W_hh from smem) =============================
    const float bhr = bhh[j], bhz = bhh[32 + j], bhn = bhh[64 + j];
    const float* gip = g_GI + (size_t)b * NSTEP * NGATE;
    float gr = gip[j], gz = gip[32 + j], gn = gip[64 + j];
    float h = 0.f;
    float* myh = hs[warp];
    const float* wrj = whr[j];
    const float* wzj = whz[j];
    const float* wnj = whn[j];

#pragma unroll 1
    for (int t = 0; t < NSTEP; t++) {
        float ngr = 0.f, ngz = 0.f, ngn = 0.f;
        if (t + 1 < NSTEP) {
            const float* q = gip + (size_t)(t + 1) * NGATE;
            ngr = q[j]; ngz = q[32 + j]; ngn = q[64 + j];
        }
        myh[j] = h;
        __syncwarp();
        float ar0 = 0.f, az0 = 0.f, an0 = 0.f;
        float ar1 = 0.f, az1 = 0.f, an1 = 0.f;
#pragma unroll
        for (int k = 0; k < 16; k++) {
            float h0 = myh[k];
            float h1 = myh[16 + k];
            ar0 = fmaf(wrj[k], h0, ar0);
            az0 = fmaf(wzj[k], h0, az0);
            an0 = fmaf(wnj[k], h0, an0);
            ar1 = fmaf(wrj[16 + k], h1, ar1);
            az1 = fmaf(wzj[16 + k], h1, az1);
            an1 = fmaf(wnj[16 + k], h1, an1);
        }
        float ar = bhr + ar0 + ar1;
        float az = bhz + az0 + az1;
        float an = bhn + an0 + an1;
        float r = sigm(gr + ar);
        float z = sigm(gz + az);
        float n = tanh_fast(gn + r * an);
        __syncwarp();
        h = (1.f - z) * n + z * h;
        gr = ngr; gz = ngz; gn = ngn;
    }

    // ================= layernorm + MLP ==================================
    float* fb = wbuf[warp];
    if (j == 0) { fb[0] = entropy; fb[1] = roc; fb[2] = corr; }
    fb[3 + j] = h;
    __syncwarp();

    float v1 = fb[j];
    float v2 = (j < 3) ? fb[32 + j] : 0.f;
    float mu = wsum(v1 + v2) * (1.f / 35.f);
    float dd1 = v1 - mu;
    float dd2 = (j < 3) ? (v2 - mu) : 0.f;
    float var = wsum(dd1 * dd1 + dd2 * dd2) * (1.f / 35.f);
    float scl = rsqrtf(var + 1e-5f);
    __syncwarp();
    fb[j] = dd1 * scl * gms[j] + bts[j];
    if (j < 3) fb[32 + j] = dd2 * scl * gms[32 + j] + bts[32 + j];
    __syncwarp();

    float* fx1 = fb + 40;
    {
        float acc0 = b1s[j], acc1 = b1s[32 + j];
#pragma unroll
        for (int k = 0; k < 35; k++) {
            float f = fb[k];
            acc0 = fmaf(w1s[j * 35 + k], f, acc0);
            acc1 = fmaf(w1s[(32 + j) * 35 + k], f, acc1);
        }
        fx1[j] = fmaxf(acc0, 0.f);
        fx1[32 + j] = fmaxf(acc1, 0.f);
    }
    __syncwarp();

    float* fx2 = fb + 104;
    {
        float acc = b2s[j];
#pragma unroll
        for (int k = 0; k < 64; k++) acc = fmaf(w2s[j * 65 + k], fx1[k], acc);
        fx2[j] = fmaxf(acc, 0.f);
    }
    __syncwarp();

    float val = -INFINITY;
    if (j < 14) {
        float acc = b3s[j];
#pragma unroll
        for (int k = 0; k < 32; k++) acc = fmaf(w3s[j * 33 + k], fx2[k], acc);
        val = acc;
    }
    int idx = j;
#pragma unroll
    for (int off = 16; off; off >>= 1) {
        float ov = __shfl_down_sync(0xffffffffu, val, off);
        int oi = __shfl_down_sync(0xffffffffu, idx, off);
        if (ov > val || (ov == val && oi < idx)) { val = ov; idx = oi; }
    }
    idx = __shfl_sync(0xffffffffu, idx, 0);

    int wl = idx + 2;
    int s_off = (wl - 1) >> 1;
    int e_off = wl >> 1;

    if (j == 0) out[b] = (float)wl;
    if (j < MAXW) {
        int offp = j - 7;
        float mval = (offp >= -s_off && offp <= e_off) ? 1.f : 0.f;
        out[(size_t)Bn + (size_t)Bn * MAXW * KDIM + (size_t)b * MAXW + j] = mval;
    }

    // ---- padded window: 3 groups of 5 rows ----
    float* pw = out + Bn;
    const float4 z4 = make_float4(0.f, 0.f, 0.f, 0.f);
    const int lo_row = 7 - s_off, hi_row = 7 + e_off;
#pragma unroll
    for (int g = 0; g < 3; g++) {
        float4 va[5], vb[5], vc[5];
#pragma unroll
        for (int r = 0; r < 5; r++) {
            int o = g * 5 + r;
            bool on = (o >= lo_row) && (o <= hi_row);
            if (on) {
                const float4* so = (const float4*)(obs + (size_t)(b * T_TOT + 7 + o) * OBS_DIM);
                va[r] = so[j];
                vb[r] = so[32 + j];
                if (j < 16) {
                    const float4* sa = (const float4*)(act + (size_t)(b * T_TOT + 7 + o) * ACT_DIM);
                    vc[r] = sa[j];
                } else vc[r] = z4;
            } else {
                va[r] = z4; vb[r] = z4; vc[r] = z4;
            }
        }
#pragma unroll
        for (int r = 0; r < 5; r++) {
            int o = g * 5 + r;
            float4* dst = (float4*)(pw + ((size_t)b * MAXW + o) * KDIM);
            dst[j] = va[r];
            dst[32 + j] = vb[r];
            if (j < 16) dst[64 + j] = vc[r];
        }
    }
}

// =====================================================================
extern "C" void kernel_launch(void* const* d_in, const int* in_sizes, int n_in,
                              void* d_out, int out_size)
{
    const float* obs = (const float*)d_in[0];
    const float* act = (const float*)d_in[1];
    const float* Wih = (const float*)d_in[2];
    const float* Whh = (const float*)d_in[3];
    const float* bih = (const float*)d_in[4];
    const float* bhh = (const float*)d_in[5];
    const float* lng = (const float*)d_in[6];
    const float* lnb = (const float*)d_in[7];
    const float* W1  = (const float*)d_in[8];
    const float* b1  = (const float*)d_in[9];
    const float* W2  = (const float*)d_in[10];
    const float* b2  = (const float*)d_in[11];
    const float* W3  = (const float*)d_in[12];
    const float* b3  = (const float*)d_in[13];

    int Bn = in_sizes[0] / (T_TOT * OBS_DIM);
    if (Bn > MAXB) Bn = MAXB;
    float* out = (float*)d_out;

    static bool attr_set = false;
    if (!attr_set) {
        cudaFuncSetAttribute(k_gemm_mma, cudaFuncAttributeMaxDynamicSharedMemorySize,
                             GEMM_SMEM_BYTES);
        attr_set = true;
    }

    k_wprep<<<(10 * 4 * NGATE * 4 + 255) / 256, 256>>>(Wih);

    int Mtot = Bn * NSTEP;
    int gemm_blocks = (Mtot + 127) / 128;
    k_gemm_mma<<<gemm_blocks, 128, GEMM_SMEM_BYTES>>>(obs, act, bih, Bn);

    int fused_blocks = (Bn + 7) / 8;
    k_fused<<<fused_blocks, 256>>>(obs, act, Whh, bhh, lng, lnb,
                                   W1, b1, W2, b2, W3, b3, out, Bn);
}

// round 12
// speedup vs baseline: 1.2264x; 1.0734x over previous
#include <cuda_runtime.h>
#include <math.h>
#include <stdint.h>

#define OBS_DIM 256
#define ACT_DIM 64
#define T_TOT   22
#define HID     32
#define MAXW    15
#define NSTEP   15
#define NGATE   96
#define KDIM    320
#define MAXB    8192

// GRU pre-activation scratch: GI[(b*15+t)*96 + g]
__device__ float g_GI[(size_t)MAXB * NSTEP * NGATE];
// W_ih fragment-packed: [kt(10)][ks(4)][bn(96)][brow(4)] float4{bh0,bh1,bl0,bl1}
__device__ __align__(16) float4 g_Wp[10 * 4 * NGATE * 4];

__device__ __forceinline__ uint32_t tf32hi_bits(float x) {
    uint32_t h;
    asm("cvt.rna.tf32.f32 %0, %1;" : "=r"(h) : "f"(x));
    return h;
}

__device__ __forceinline__ void mma_tf32(float* c, uint32_t a0, uint32_t a1,
                                         uint32_t a2, uint32_t a3,
                                         uint32_t b0, uint32_t b1) {
    asm volatile(
        "mma.sync.aligned.m16n8k8.row.col.f32.tf32.tf32.f32 "
        "{%0,%1,%2,%3}, {%4,%5,%6,%7}, {%8,%9}, {%0,%1,%2,%3};\n"
        : "+f"(c[0]), "+f"(c[1]), "+f"(c[2]), "+f"(c[3])
        : "r"(a0), "r"(a1), "r"(a2), "r"(a3), "r"(b0), "r"(b1));
}

// ---------- cp.async ----------
__device__ __forceinline__ void cp16(uint32_t dst, const void* src) {
    asm volatile("cp.async.ca.shared.global [%0], [%1], 16;"
                 :: "r"(dst), "l"(src) : "memory");
}
__device__ __forceinline__ void cp_commit() {
    asm volatile("cp.async.commit_group;" ::: "memory");
}
template <int N>
__device__ __forceinline__ void cp_wait() {
    asm volatile("cp.async.wait_group %0;" :: "n"(N) : "memory");
}

__device__ __forceinline__ float wsum(float x) {
#pragma unroll
    for (int o = 16; o; o >>= 1) x += __shfl_xor_sync(0xffffffffu, x, o);
    return x;
}
__device__ __forceinline__ float wmax(float x) {
#pragma unroll
    for (int o = 16; o; o >>= 1) x = fmaxf(x, __shfl_xor_sync(0xffffffffu, x, o));
    return x;
}
__device__ __forceinline__ float sigm(float x) { return 1.f / (1.f + __expf(-x)); }
__device__ __forceinline__ float tanh_fast(float x) {
    float e = __expf(-2.f * fabsf(x));
    float r = (1.f - e) / (1.f + e);
    return copysignf(r, x);
}

// =====================================================================
// Kernel 0: pack W_ih into fragment-ready tf32 hi/lo quads.
// =====================================================================
__global__ void k_wprep(const float* __restrict__ Wih) {
    int p = blockIdx.x * 256 + threadIdx.x;
    if (p >= 10 * 4 * NGATE * 4) return;
    int brow = p & 3;
    int t = p >> 2;
    int bn = t % NGATE;
    int kk8 = t / NGATE;              // 0..39
    int k = kk8 * 8 + brow;
    float x0 = Wih[(size_t)bn * KDIM + k];
    float x1 = Wih[(size_t)bn * KDIM + k + 4];
    float h0 = __uint_as_float(tf32hi_bits(x0));
    float h1 = __uint_as_float(tf32hi_bits(x1));
    g_Wp[p] = make_float4(h0, h1, x0 - h0, x1 - h1);
}

// =====================================================================
// Kernel 1: tensor-core GEMM, cp.async double-buffered.
// GI[M=Bn*15,96] = X[M,320] @ W^T + b ; X fp32 in smem, split in regs.
// CTA: 128 thr, tile 128m x 96n, warp tile 32m x 96n.
// =====================================================================
#define XSTR 36
#define XTILE (128 * XSTR)                 // floats per X buffer (4608)
#define WTILE (4 * NGATE * 4)              // float4s per W k-tile (1536)
#define GEMM_SMEM_BYTES (2 * XTILE * 4 + 2 * WTILE * 16)   // 86016

__global__ __launch_bounds__(128) void k_gemm_mma(
    const float* __restrict__ obs, const float* __restrict__ act,
    const float* __restrict__ bih, int Bn)
{
    extern __shared__ __align__(16) float4 smem4[];
    float*  Xs = (float*)smem4;                     // [2][128][XSTR] fp32
    float4* Wp = smem4 + (2 * XTILE) / 4;           // [2][4][96][4]
    __shared__ float sbias[96];

    const int tid = threadIdx.x;
    const int warp = tid >> 5, lane = tid & 31;
    const int Mtot = Bn * NSTEP;
    const int m_base = blockIdx.x * 128;

    if (tid < 96) sbias[tid] = bih[tid];

    // per-thread X-load row indices (8 rows, fixed across k-tiles)
    int rowptr[8];
#pragma unroll
    for (int i = 0; i < 8; i++) {
        int idx = i * 128 + tid;
        int r = idx >> 3;
        int gm = m_base + r;
        int gmc = gm < Mtot ? gm : Mtot - 1;
        int bb = gmc / NSTEP;
        int tt = gmc - bb * NSTEP;
        rowptr[i] = bb * T_TOT + tt;
    }
    const int c4 = tid & 7;

    const uint32_t xs_addr = (uint32_t)__cvta_generic_to_shared(Xs);
    const uint32_t wp_addr = (uint32_t)__cvta_generic_to_shared(Wp);

    auto load_tile = [&](int pb, int kt) {
        const int k0 = kt * 32;
        const uint32_t xb = xs_addr + (uint32_t)pb * XTILE * 4;
#pragma unroll
        for (int i = 0; i < 8; i++) {
            int idx = i * 128 + tid;
            int r = idx >> 3;
            int kk = k0 + c4 * 4;
            const float* src = (k0 < OBS_DIM)
                ? obs + (size_t)rowptr[i] * OBS_DIM + kk
                : act + (size_t)rowptr[i] * ACT_DIM + (kk - OBS_DIM);
            cp16(xb + (uint32_t)(r * XSTR + c4 * 4) * 4, src);
        }
        const uint32_t wb = wp_addr + (uint32_t)pb * WTILE * 16;
        const float4* gW = g_Wp + (size_t)kt * WTILE;
#pragma unroll
        for (int i = 0; i < 12; i++) {
            int idx = i * 128 + tid;
            cp16(wb + (uint32_t)idx * 16, gW + idx);
        }
    };

    float acc[2][12][4];
#pragma unroll
    for (int mt = 0; mt < 2; mt++)
#pragma unroll
        for (int nt = 0; nt < 12; nt++)
#pragma unroll
            for (int q = 0; q < 4; q++) acc[mt][nt][q] = 0.f;

    const int ar = lane >> 2, ac = lane & 3;
    const int brow = lane & 3, bcol = lane >> 2;
    const int m0 = warp * 32;

    load_tile(0, 0);
    cp_commit();

#pragma unroll 1
    for (int kt = 0; kt < 10; kt++) {
        const int pb = kt & 1;
        if (kt + 1 < 10) {
            load_tile((kt + 1) & 1, kt + 1);
            cp_commit();
            cp_wait<1>();
        } else {
            cp_wait<0>();
        }
        __syncthreads();

        const float* xp = Xs + pb * XTILE;
        const float4* wp = Wp + pb * WTILE;

#pragma unroll
        for (int ks = 0; ks < 4; ks++) {
            const int kk = ks * 8;
            // A fragments: load fp32, split to tf32 hi/lo in registers
            uint32_t ah[2][4], al[2][4];
#pragma unroll
            for (int mt = 0; mt < 2; mt++) {
                int mr = m0 + mt * 16 + ar;
                float x0 = xp[mr * XSTR + kk + ac];
                float x1 = xp[(mr + 8) * XSTR + kk + ac];
                float x2 = xp[mr * XSTR + kk + ac + 4];
                float x3 = xp[(mr + 8) * XSTR + kk + ac + 4];
                uint32_t h0 = tf32hi_bits(x0);
                uint32_t h1 = tf32hi_bits(x1);
                uint32_t h2 = tf32hi_bits(x2);
                uint32_t h3 = tf32hi_bits(x3);
                ah[mt][0] = h0; al[mt][0] = __float_as_uint(x0 - __uint_as_float(h0));
                ah[mt][1] = h1; al[mt][1] = __float_as_uint(x1 - __uint_as_float(h1));
                ah[mt][2] = h2; al[mt][2] = __float_as_uint(x2 - __uint_as_float(h2));
                ah[mt][3] = h3; al[mt][3] = __float_as_uint(x3 - __uint_as_float(h3));
            }
            const float4* wrow = wp + ks * (NGATE * 4);
#pragma unroll
            for (int nt = 0; nt < 12; nt++) {
                float4 bf = wrow[(nt * 8 + bcol) * 4 + brow];
                uint32_t bh0 = __float_as_uint(bf.x);
                uint32_t bh1 = __float_as_uint(bf.y);
                uint32_t bl0 = __float_as_uint(bf.z);
                uint32_t bl1 = __float_as_uint(bf.w);
#pragma unroll
                for (int mt = 0; mt < 2; mt++) {
                    mma_tf32(acc[mt][nt], ah[mt][0], ah[mt][1], ah[mt][2], ah[mt][3], bh0, bh1);
                    mma_tf32(acc[mt][nt], ah[mt][0], ah[mt][1], ah[mt][2], ah[mt][3], bl0, bl1);
                    mma_tf32(acc[mt][nt], al[mt][0], al[mt][1], al[mt][2], al[mt][3], bh0, bh1);
                }
            }
        }
        __syncthreads();
    }

    // ---- epilogue: C fragments -> GI with bias ----
#pragma unroll
    for (int mt = 0; mt < 2; mt++) {
        const int r0 = m_base + m0 + mt * 16 + (lane >> 2);
        const int r1 = r0 + 8;
#pragma unroll
        for (int nt = 0; nt < 12; nt++) {
            int cc = nt * 8 + 2 * (lane & 3);
            float bx = sbias[cc], by = sbias[cc + 1];
            if (r0 < Mtot) {
                float2 o = make_float2(acc[mt][nt][0] + bx, acc[mt][nt][1] + by);
                *(float2*)(g_GI + (size_t)r0 * NGATE + cc) = o;
            }
            if (r1 < Mtot) {
                float2 o = make_float2(acc[mt][nt][2] + bx, acc[mt][nt][3] + by);
                *(float2*)(g_GI + (size_t)r1 * NGATE + cc) = o;
            }
        }
    }
}

// =====================================================================
// Kernel 2 (fused, R9 known-good 96.5us)
// =====================================================================
__global__ __launch_bounds__(256, 3) void k_fused(
    const float* __restrict__ obs, const float* __restrict__ act,
    const float* __restrict__ Whh, const float* __restrict__ bhh,
    const float* __restrict__ lng, const float* __restrict__ lnb,
    const float* __restrict__ W1, const float* __restrict__ b1,
    const float* __restrict__ W2, const float* __restrict__ b2,
    const float* __restrict__ W3, const float* __restrict__ b3,
    float* __restrict__ out, int Bn)
{
    __shared__ float whr[32][33], whz[32][33], whn[32][33];
    __shared__ float w1s[64 * 35];
    __shared__ float w2s[32 * 65];
    __shared__ float w3s[14 * 33];
    __shared__ float b1s[64], b2s[32], b3s[14];
    __shared__ float gms[35], bts[35];
    __shared__ float wbuf[8][144];
    __shared__ float hs[8][32];

    const int tid = threadIdx.x;
    for (int i = tid; i < 3 * HID * HID; i += 256) {
        int row = i >> 5, k = i & 31;
        float v = Whh[i];
        if (row < 32)       whr[row][k] = v;
        else if (row < 64)  whz[row - 32][k] = v;
        else                whn[row - 64][k] = v;
    }
    for (int i = tid; i < 64 * 35; i += 256) w1s[i] = W1[i];
    for (int i = tid; i < 32 * 64; i += 256) w2s[(i >> 6) * 65 + (i & 63)] = W2[i];
    for (int i = tid; i < 14 * 32; i += 256) w3s[(i >> 5) * 33 + (i & 31)] = W3[i];
    if (tid < 64) b1s[tid] = b1[tid];
    if (tid < 32) b2s[tid] = b2[tid];
    if (tid < 14) b3s[tid] = b3[tid];
    if (tid < 35) { gms[tid] = lng[tid]; bts[tid] = lnb[tid]; }
    __syncthreads();

    const int warp = tid >> 5, j = tid & 31;
    const int b = blockIdx.x * 8 + warp;
    if (b >= Bn) return;

    // ================= features FIRST ===================================
    float entropy, roc, corr;
    {
        const float* op = obs + (size_t)b * T_TOT * OBS_DIM;
        float o11[8], o12[8], o13[8], o14[8];
#pragma unroll
        for (int i = 0; i < 8; i++) {
            o11[i] = op[11 * OBS_DIM + i * 32 + j];
            o12[i] = op[12 * OBS_DIM + i * 32 + j];
            o13[i] = op[13 * OBS_DIM + i * 32 + j];
            o14[i] = op[14 * OBS_DIM + i * 32 + j];
        }

        float mx = o14[0];
#pragma unroll
        for (int i = 1; i < 8; i++) mx = fmaxf(mx, o14[i]);
        mx = wmax(mx);
        float s = 0.f;
#pragma unroll
        for (int i = 0; i < 8; i++) s += __expf(o14[i] - mx);
        s = wsum(s);
        float inv_s = 1.f / s;
        float es = 0.f;
#pragma unroll
        for (int i = 0; i < 8; i++) {
            float p = __expf(o14[i] - mx) * inv_s;
            es += p * __logf(p + 1e-8f);
        }
        es = wsum(es);
        entropy = -es;

        float d2a = 0.f, d2b = 0.f, d2c = 0.f;
#pragma unroll
        for (int i = 0; i < 8; i++) {
            float da = o12[i] - o11[i]; d2a = fmaf(da, da, d2a);
            float db = o13[i] - o12[i]; d2b = fmaf(db, db, d2b);
            float dc = o14[i] - o13[i]; d2c = fmaf(dc, dc, d2c);
        }
        d2a = wsum(d2a); d2b = wsum(d2b); d2c = wsum(d2c);
        roc = (sqrtf(d2a) + sqrtf(d2b) + sqrtf(d2c)) * (1.f / 3.f);

        float osum = 0.f;
#pragma unroll
        for (int i = 0; i < 8; i++) osum += o14[i];
        osum = wsum(osum);
        float om = osum * (1.f / 256.f);
        const float* ap = act + ((size_t)b * T_TOT + 13) * ACT_DIM;
        float a0 = ap[j], a1 = ap[32 + j];
        float am = wsum(a0 + a1) * (1.f / 256.f);
        float num = 0.f, do2 = 0.f;
#pragma unroll
        for (int i = 0; i < 8; i++) {
            float oc = o14[i] - om;
            do2 = fmaf(oc, oc, do2);
            float acv = ((i == 0) ? a0 : (i == 1) ? a1 : 0.f) - am;
            num = fmaf(oc, acv, num);
        }
        float da2 = (a0 - am) * (a0 - am) + (a1 - am) * (a1 - am) + 6.f * am * am;
        num = wsum(num); do2 = wsum(do2); da2 = wsum(da2);
        corr = num / (sqrtf(do2) * sqrtf(da2) + 1e-8f);
    }

    // ================= GRU (W_hh from smem) =============================
    const float bhr = bhh[j], bhz = bhh[32 + j], bhn = bhh[64 + j];
    const float* gip = g_GI + (size_t)b * NSTEP * NGATE;
    float gr = gip[j], gz = gip[32 + j], gn = gip[64 + j];
    float h = 0.f;
    float* myh = hs[warp];
    const float* wrj = whr[j];
    const float* wzj = whz[j];
    const float* wnj = whn[j];

#pragma unroll 1
    for (int t = 0; t < NSTEP; t++) {
        float ngr = 0.f, ngz = 0.f, ngn = 0.f;
        if (t + 1 < NSTEP) {
            const float* q = gip + (size_t)(t + 1) * NGATE;
            ngr = q[j]; ngz = q[32 + j]; ngn = q[64 + j];
        }
        myh[j] = h;
        __syncwarp();
        float ar0 = 0.f, az0 = 0.f, an0 = 0.f;
        float ar1 = 0.f, az1 = 0.f, an1 = 0.f;
#pragma unroll
        for (int k = 0; k < 16; k++) {
            float h0 = myh[k];
            float h1 = myh[16 + k];
            ar0 = fmaf(wrj[k], h0, ar0);
            az0 = fmaf(wzj[k], h0, az0);
            an0 = fmaf(wnj[k], h0, an0);
            ar1 = fmaf(wrj[16 + k], h1, ar1);
            az1 = fmaf(wzj[16 + k], h1, az1);
            an1 = fmaf(wnj[16 + k], h1, an1);
        }
        float ar = bhr + ar0 + ar1;
        float az = bhz + az0 + az1;
        float an = bhn + an0 + an1;
        float r = sigm(gr + ar);
        float z = sigm(gz + az);
        float n = tanh_fast(gn + r * an);
        __syncwarp();
        h = (1.f - z) * n + z * h;
        gr = ngr; gz = ngz; gn = ngn;
    }

    // ================= layernorm + MLP ==================================
    float* fb = wbuf[warp];
    if (j == 0) { fb[0] = entropy; fb[1] = roc; fb[2] = corr; }
    fb[3 + j] = h;
    __syncwarp();

    float v1 = fb[j];
    float v2 = (j < 3) ? fb[32 + j] : 0.f;
    float mu = wsum(v1 + v2) * (1.f / 35.f);
    float dd1 = v1 - mu;
    float dd2 = (j < 3) ? (v2 - mu) : 0.f;
    float var = wsum(dd1 * dd1 + dd2 * dd2) * (1.f / 35.f);
    float scl = rsqrtf(var + 1e-5f);
    __syncwarp();
    fb[j] = dd1 * scl * gms[j] + bts[j];
    if (j < 3) fb[32 + j] = dd2 * scl * gms[32 + j] + bts[32 + j];
    __syncwarp();

    float* fx1 = fb + 40;
    {
        float acc0 = b1s[j], acc1 = b1s[32 + j];
#pragma unroll
        for (int k = 0; k < 35; k++) {
            float f = fb[k];
            acc0 = fmaf(w1s[j * 35 + k], f, acc0);
            acc1 = fmaf(w1s[(32 + j) * 35 + k], f, acc1);
        }
        fx1[j] = fmaxf(acc0, 0.f);
        fx1[32 + j] = fmaxf(acc1, 0.f);
    }
    __syncwarp();

    float* fx2 = fb + 104;
    {
        float acc = b2s[j];
#pragma unroll
        for (int k = 0; k < 64; k++) acc = fmaf(w2s[j * 65 + k], fx1[k], acc);
        fx2[j] = fmaxf(acc, 0.f);
    }
    __syncwarp();

    float val = -INFINITY;
    if (j < 14) {
        float acc = b3s[j];
#pragma unroll
        for (int k = 0; k < 32; k++) acc = fmaf(w3s[j * 33 + k], fx2[k], acc);
        val = acc;
    }
    int idx = j;
#pragma unroll
    for (int off = 16; off; off >>= 1) {
        float ov = __shfl_down_sync(0xffffffffu, val, off);
        int oi = __shfl_down_sync(0xffffffffu, idx, off);
        if (ov > val || (ov == val && oi < idx)) { val = ov; idx = oi; }
    }
    idx = __shfl_sync(0xffffffffu, idx, 0);

    int wl = idx + 2;
    int s_off = (wl - 1) >> 1;
    int e_off = wl >> 1;

    if (j == 0) out[b] = (float)wl;
    if (j < MAXW) {
        int offp = j - 7;
        float mval = (offp >= -s_off && offp <= e_off) ? 1.f : 0.f;
        out[(size_t)Bn + (size_t)Bn * MAXW * KDIM + (size_t)b * MAXW + j] = mval;
    }

    // ---- padded window: 3 groups of 5 rows ----
    float* pw = out + Bn;
    const float4 z4 = make_float4(0.f, 0.f, 0.f, 0.f);
    const int lo_row = 7 - s_off, hi_row = 7 + e_off;
#pragma unroll
    for (int g = 0; g < 3; g++) {
        float4 va[5], vb[5], vc[5];
#pragma unroll
        for (int r = 0; r < 5; r++) {
            int o = g * 5 + r;
            bool on = (o >= lo_row) && (o <= hi_row);
            if (on) {
                const float4* so = (const float4*)(obs + (size_t)(b * T_TOT + 7 + o) * OBS_DIM);
                va[r] = so[j];
                vb[r] = so[32 + j];
                if (j < 16) {
                    const float4* sa = (const float4*)(act + (size_t)(b * T_TOT + 7 + o) * ACT_DIM);
                    vc[r] = sa[j];
                } else vc[r] = z4;
            } else {
                va[r] = z4; vb[r] = z4; vc[r] = z4;
            }
        }
#pragma unroll
        for (int r = 0; r < 5; r++) {
            int o = g * 5 + r;
            float4* dst = (float4*)(pw + ((size_t)b * MAXW + o) * KDIM);
            dst[j] = va[r];
            dst[32 + j] = vb[r];
            if (j < 16) dst[64 + j] = vc[r];
        }
    }
}

// =====================================================================
extern "C" void kernel_launch(void* const* d_in, const int* in_sizes, int n_in,
                              void* d_out, int out_size)
{
    const float* obs = (const float*)d_in[0];
    const float* act = (const float*)d_in[1];
    const float* Wih = (const float*)d_in[2];
    const float* Whh = (const float*)d_in[3];
    const float* bih = (const float*)d_in[4];
    const float* bhh = (const float*)d_in[5];
    const float* lng = (const float*)d_in[6];
    const float* lnb = (const float*)d_in[7];
    const float* W1  = (const float*)d_in[8];
    const float* b1  = (const float*)d_in[9];
    const float* W2  = (const float*)d_in[10];
    const float* b2  = (const float*)d_in[11];
    const float* W3  = (const float*)d_in[12];
    const float* b3  = (const float*)d_in[13];

    int Bn = in_sizes[0] / (T_TOT * OBS_DIM);
    if (Bn > MAXB) Bn = MAXB;
    float* out = (float*)d_out;

    static bool attr_set = false;
    if (!attr_set) {
        cudaFuncSetAttribute(k_gemm_mma, cudaFuncAttributeMaxDynamicSharedMemorySize,
                             GEMM_SMEM_BYTES);
        attr_set = true;
    }

    k_wprep<<<(10 * 4 * NGATE * 4 + 255) / 256, 256>>>(Wih);

    int Mtot = Bn * NSTEP;
    int gemm_blocks = (Mtot + 127) / 128;
    k_gemm_mma<<<gemm_blocks, 128, GEMM_SMEM_BYTES>>>(obs, act, bih, Bn);

    int fused_blocks = (Bn + 7) / 8;
    k_fused<<<fused_blocks, 256>>>(obs, act, Whh, bhh, lng, lnb,
                                   W1, b1, W2, b2, W3, b3, out, Bn);
}